// round 1
// baseline (speedup 1.0000x reference)
#include <cuda_runtime.h>
#include <math.h>

// Problem constants
#define N_B     32
#define C_DIM   384
#define HW      3136        // 56*56
#define M_DIM   8
#define D_MODEL 768
#define E_DIM   768         // 2*C

// ---------------- scratch for clipped KV (allowed: __device__ global) ----------
__device__ float g_kv[N_B * M_DIM * E_DIM];   // [n][m][e], e<384 = K, e>=384 = V

// ================= Kernel 1: kv = clip(gf @ W^T + b, 0, 6) =====================
// A = gf flattened (256 x 768), C[r][e] = sum_d A[r][d] * W[e][d]
#define BM 32
#define BN 64
#define BK 32

__global__ __launch_bounds__(256) void kv_gemm_kernel(
    const float* __restrict__ gf,
    const float* __restrict__ W,
    const float* __restrict__ bias)
{
    __shared__ float As[BK][BM + 2];   // pad 34 (keeps float2 reads 8B aligned)
    __shared__ float Bs[BK][BN + 4];   // pad 68 (keeps float4 reads 16B aligned)

    const int tid = threadIdx.x;
    const int tx  = tid & 15;          // 16 col-groups  -> e = tx*4
    const int ty  = tid >> 4;          // 16 row-groups  -> r = ty*2
    const int rb  = blockIdx.y * BM;
    const int eb  = blockIdx.x * BN;

    float acc[2][4];
    #pragma unroll
    for (int i = 0; i < 2; i++)
        #pragma unroll
        for (int j = 0; j < 4; j++) acc[i][j] = 0.f;

    for (int kb = 0; kb < D_MODEL; kb += BK) {
        // Load A tile (32x32), coalesced per row
        #pragma unroll
        for (int i = 0; i < 4; i++) {
            int idx = tid + i * 256;
            int r  = idx >> 5;
            int kk = idx & 31;
            As[kk][r] = gf[(size_t)(rb + r) * D_MODEL + kb + kk];
        }
        // Load B tile (64x32 of W), coalesced per row, stored transposed
        #pragma unroll
        for (int i = 0; i < 8; i++) {
            int idx = tid + i * 256;
            int e  = idx >> 5;
            int kk = idx & 31;
            Bs[kk][e] = W[(size_t)(eb + e) * D_MODEL + kb + kk];
        }
        __syncthreads();

        #pragma unroll
        for (int kk = 0; kk < BK; kk++) {
            float2 av = *(const float2*)&As[kk][ty * 2];
            float4 bv = *(const float4*)&Bs[kk][tx * 4];
            acc[0][0] += av.x * bv.x; acc[0][1] += av.x * bv.y;
            acc[0][2] += av.x * bv.z; acc[0][3] += av.x * bv.w;
            acc[1][0] += av.y * bv.x; acc[1][1] += av.y * bv.y;
            acc[1][2] += av.y * bv.z; acc[1][3] += av.y * bv.w;
        }
        __syncthreads();
    }

    float4 bb = *(const float4*)&bias[eb + tx * 4];
    #pragma unroll
    for (int r = 0; r < 2; r++) {
        float4 o;
        o.x = fminf(fmaxf(acc[r][0] + bb.x, 0.f), 6.f);
        o.y = fminf(fmaxf(acc[r][1] + bb.y, 0.f), 6.f);
        o.z = fminf(fmaxf(acc[r][2] + bb.z, 0.f), 6.f);
        o.w = fminf(fmaxf(acc[r][3] + bb.w, 0.f), 6.f);
        *(float4*)&g_kv[(size_t)(rb + ty * 2 + r) * E_DIM + eb + tx * 4] = o;
    }
}

// ================= Kernel 2: attention + residual ==============================
// Per block: batch n, pixel tile of 112. x tile (384ch x 112px) staged in smem,
// read from HBM exactly once. 448 threads = 4 channel-quarters x 112 pixels.
#define TILE_P    112
#define NTHREADS2 448
#define CQ        96       // channels per quarter

// smem carve (floats): xs 43008 | Ks 3072 | Vs 3072 | part 3584 | attn 896
#define SM_XS    0
#define SM_KS    43008
#define SM_VS    46080
#define SM_PART  49152
#define SM_ATTN  52736
#define SM_FLOATS 53632
#define SM_BYTES (SM_FLOATS * 4)   // 214528

__global__ __launch_bounds__(NTHREADS2) void attn_kernel(
    const float* __restrict__ x,
    float* __restrict__ out)
{
    extern __shared__ float sm[];
    float* xs   = sm + SM_XS;     // [c][p]  (c*112 + p)
    float* Ks   = sm + SM_KS;     // [k][c]  (k*384 + c)
    float* Vs   = sm + SM_VS;     // [k][c]
    float* part = sm + SM_PART;   // [(q*112+p)*8 + k]
    float* attn = sm + SM_ATTN;   // [p*8 + k]

    const int tid  = threadIdx.x;
    const int n    = blockIdx.y;
    const int tile = blockIdx.x;
    const int p0   = tile * TILE_P;

    // ---- load K,V for batch n (float4, 16B aligned) ----
    {
        const float4* kv4 = (const float4*)(g_kv + (size_t)n * (M_DIM * E_DIM));
        for (int i = tid; i < (M_DIM * E_DIM) / 4; i += NTHREADS2) {
            int m = i / 192;          // 768/4 float4 per row
            int j = i - m * 192;
            float4 v = kv4[i];
            int e = j * 4;
            if (e < C_DIM) *(float4*)&Ks[m * C_DIM + e] = v;
            else           *(float4*)&Vs[m * C_DIM + (e - C_DIM)] = v;
        }
    }

    // ---- load x tile: 384 rows x 112 px, float4 coalesced ----
    {
        const float* xb = x + (size_t)n * C_DIM * HW + p0;
        for (int i = tid; i < C_DIM * (TILE_P / 4); i += NTHREADS2) {
            int c = i / 28;           // 112/4 float4 per row
            int j = i - c * 28;
            float4 v = *(const float4*)(xb + (size_t)c * HW + j * 4);
            *(float4*)&xs[c * TILE_P + j * 4] = v;
        }
    }
    __syncthreads();

    const int q  = tid / TILE_P;
    const int p  = tid - q * TILE_P;
    const int c0 = q * CQ;

    // ---- partial scores over this quarter's channels ----
    float acc[8];
    #pragma unroll
    for (int k = 0; k < 8; k++) acc[k] = 0.f;

    for (int c = c0; c < c0 + CQ; c += 4) {
        float x0 = xs[(c + 0) * TILE_P + p];
        float x1 = xs[(c + 1) * TILE_P + p];
        float x2 = xs[(c + 2) * TILE_P + p];
        float x3 = xs[(c + 3) * TILE_P + p];
        #pragma unroll
        for (int k = 0; k < 8; k++) {
            float4 kk = *(const float4*)&Ks[k * C_DIM + c];
            acc[k] += x0 * kk.x + x1 * kk.y + x2 * kk.z + x3 * kk.w;
        }
    }
    {
        float* pp = &part[(q * TILE_P + p) * 8];
        *(float4*)(pp + 0) = make_float4(acc[0], acc[1], acc[2], acc[3]);
        *(float4*)(pp + 4) = make_float4(acc[4], acc[5], acc[6], acc[7]);
    }
    __syncthreads();

    // ---- softmax over k=8 (112 threads, one per pixel) ----
    if (tid < TILE_P) {
        float s[8];
        #pragma unroll
        for (int k = 0; k < 8; k++) s[k] = 0.f;
        #pragma unroll
        for (int qq = 0; qq < 4; qq++) {
            const float* sp = &part[(qq * TILE_P + tid) * 8];
            float4 u0 = *(const float4*)(sp + 0);
            float4 u1 = *(const float4*)(sp + 4);
            s[0] += u0.x; s[1] += u0.y; s[2] += u0.z; s[3] += u0.w;
            s[4] += u1.x; s[5] += u1.y; s[6] += u1.z; s[7] += u1.w;
        }
        float mx = s[0];
        #pragma unroll
        for (int k = 1; k < 8; k++) mx = fmaxf(mx, s[k]);
        float sum = 0.f;
        #pragma unroll
        for (int k = 0; k < 8; k++) { s[k] = __expf(s[k] - mx); sum += s[k]; }
        float inv = 1.0f / sum;
        float* ap = &attn[tid * 8];
        *(float4*)(ap + 0) = make_float4(s[0] * inv, s[1] * inv, s[2] * inv, s[3] * inv);
        *(float4*)(ap + 4) = make_float4(s[4] * inv, s[5] * inv, s[6] * inv, s[7] * inv);
    }
    __syncthreads();

    // ---- output: out = x + attn @ V, this quarter's channels ----
    float a[8];
    {
        const float* ap = &attn[p * 8];
        float4 u0 = *(const float4*)(ap + 0);
        float4 u1 = *(const float4*)(ap + 4);
        a[0] = u0.x; a[1] = u0.y; a[2] = u0.z; a[3] = u0.w;
        a[4] = u1.x; a[5] = u1.y; a[6] = u1.z; a[7] = u1.w;
    }
    float* ob = out + (size_t)n * C_DIM * HW + p0 + p;
    for (int c = c0; c < c0 + CQ; c += 4) {
        float o0 = xs[(c + 0) * TILE_P + p];
        float o1 = xs[(c + 1) * TILE_P + p];
        float o2 = xs[(c + 2) * TILE_P + p];
        float o3 = xs[(c + 3) * TILE_P + p];
        #pragma unroll
        for (int k = 0; k < 8; k++) {
            float4 vv = *(const float4*)&Vs[k * C_DIM + c];
            o0 += a[k] * vv.x; o1 += a[k] * vv.y;
            o2 += a[k] * vv.z; o3 += a[k] * vv.w;
        }
        ob[(size_t)(c + 0) * HW] = o0;
        ob[(size_t)(c + 1) * HW] = o1;
        ob[(size_t)(c + 2) * HW] = o2;
        ob[(size_t)(c + 3) * HW] = o3;
    }
}

// ================= launch ======================================================
extern "C" void kernel_launch(void* const* d_in, const int* in_sizes, int n_in,
                              void* d_out, int out_size)
{
    const float* x  = (const float*)d_in[0];
    const float* gf = (const float*)d_in[1];
    const float* W  = (const float*)d_in[2];
    const float* b  = (const float*)d_in[3];
    float* out = (float*)d_out;

    // Stage 1: KV projection + clip  (96 blocks)
    kv_gemm_kernel<<<dim3(E_DIM / BN, (N_B * M_DIM) / BM), 256>>>(gf, W, b);

    // Stage 2: attention + residual (28 tiles x 32 batches)
    cudaFuncSetAttribute(attn_kernel, cudaFuncAttributeMaxDynamicSharedMemorySize, SM_BYTES);
    attn_kernel<<<dim3(HW / TILE_P, N_B), NTHREADS2, SM_BYTES>>>(x, out);
}